// round 12
// baseline (speedup 1.0000x reference)
#include <cuda_runtime.h>
#include <cuda_fp16.h>

#define NN 50000
#define EE 1200000
#define GG 256
#define CC 10
#define NB 196   // scan blocks: ceil(NN/256)

// ---------------- scratch (device globals; no allocation allowed) ----------
__device__ __align__(16) float d_deg[NN];        // dinv
__device__ __align__(16) int   d_cnts[NN];       // in-degree (int)
__device__ __align__(16) int   d_rowptr[NN + 1];
__device__ __align__(16) int   d_cur[NN];        // fill cursors
__device__ __align__(16) int   d_bsum[NB];
__device__ __align__(16) int2  d_csr[EE];        // {src, bitcast(dinv[src])}
__device__ __align__(16) __half d_h16[NN * 64];  // post-GEMM features (fp16)
__device__ __align__(16) float d_agg[NN * 64];   // aggregated (pre-BN, fp32)
__device__ __align__(16) float d_bnbuf[2][128];  // BN sums, double-buffered
__device__ __align__(16) float d_pool[GG * 32];
__device__ __align__(16) float d_cnt[GG];

__device__ __forceinline__ void red4(float* p, float a, float b, float c, float d) {
    asm volatile("red.global.add.v4.f32 [%0], {%1,%2,%3,%4};"
                 :: "l"(p), "f"(a), "f"(b), "f"(c), "f"(d) : "memory");
}

// ---------------- setup ------------------------------------------------------
__global__ void count_deg(const int* __restrict__ dst) {
    int i = blockIdx.x * blockDim.x + threadIdx.x;
    if (i < EE) atomicAdd(&d_cnts[dst[i]], 1);
}

// per-256-block degree sums (for scan) + dinv
__global__ void scan_bsum() {
    int i = blockIdx.x * 256 + threadIdx.x;
    int v = (i < NN) ? d_cnts[i] : 0;
    if (i < NN) d_deg[i] = rsqrtf((float)v + 1.f);
#pragma unroll
    for (int o = 16; o > 0; o >>= 1) v += __shfl_down_sync(0xffffffffu, v, o);
    __shared__ int sh[8];
    if ((threadIdx.x & 31) == 0) sh[threadIdx.x >> 5] = v;
    __syncthreads();
    if (threadIdx.x == 0) {
        int s = 0;
#pragma unroll
        for (int w = 0; w < 8; w++) s += sh[w];
        d_bsum[blockIdx.x] = s;
    }
}

// exclusive scan -> rowptr + cursors; each block redundantly reduces its d_bsum prefix
__global__ void scan_final() {
    __shared__ int sh[256];
    __shared__ int wsum[8];
    int tid = threadIdx.x;
    int pv = (tid < blockIdx.x) ? d_bsum[tid] : 0;   // NB=196 < 256
#pragma unroll
    for (int o = 16; o > 0; o >>= 1) pv += __shfl_down_sync(0xffffffffu, pv, o);
    if ((tid & 31) == 0) wsum[tid >> 5] = pv;
    __syncthreads();
    int boff = 0;
#pragma unroll
    for (int w = 0; w < 8; w++) boff += wsum[w];

    int i = blockIdx.x * 256 + tid;
    int v = (i < NN) ? d_cnts[i] : 0;
    sh[tid] = v;
    __syncthreads();
#pragma unroll
    for (int o = 1; o < 256; o <<= 1) {
        int t = (tid >= o) ? sh[tid - o] : 0;
        __syncthreads();
        sh[tid] += t;
        __syncthreads();
    }
    if (i < NN) {
        int excl = sh[tid] - v + boff;
        d_rowptr[i] = excl;
        d_cur[i] = excl;
    }
    if (blockIdx.x == NB - 1 && tid == 255) d_rowptr[NN] = boff + sh[255];
}

__global__ void fill_csr(const int* __restrict__ src, const int* __restrict__ dst) {
    int e = blockIdx.x * blockDim.x + threadIdx.x;
    if (e >= EE) return;
    int s = src[e], d = dst[e];
    int pos = atomicAdd(&d_cur[d], 1);
    d_csr[pos] = make_int2(s, __float_as_int(d_deg[s]));
}

// ---------------- register-tiled GEMM, fused BN+ReLU on input, fp16 output --
// h16 = relu(BN(in)) @ W ; block 0 zeroes bnzero (this layer's stats buffer).
// xs stride 68 floats: 8-lane LDS.128 phases hit 8 distinct 4-bank groups.
template <int FOUT>
__global__ void gemm_k(const float* __restrict__ xin, const float* __restrict__ W,
                       const float* __restrict__ bnin, const float* __restrict__ g,
                       const float* __restrict__ be, float* __restrict__ bnzero) {
    constexpr int CG = FOUT / 4;      // col groups   (16 or 8)
    constexpr int NG = 256 / CG;      // node groups  (16 or 32)
    constexpr int NODES = NG * 4;     // 64 or 128 nodes per block
    constexpr int XP = 68;            // xs row stride (floats)
    __shared__ float Ws[64 * FOUT];
    __shared__ float xs[NODES * XP];
    __shared__ float scale[64], shift[64];

    const float* in = xin ? xin : d_agg;
    int tid = threadIdx.x;
    if (bnin && tid < 64) {
        const float invn = 1.f / (float)NN;
        float mu = bnin[tid] * invn;
        float var = bnin[64 + tid] * invn - mu * mu;
        float s = g[tid] * rsqrtf(var + 1e-5f);
        scale[tid] = s;
        shift[tid] = fmaf(-mu, s, be[tid]);
    }
    if (blockIdx.x == 0 && tid < 128) bnzero[tid] = 0.f;
    for (int i = tid; i < 64 * FOUT; i += 256) Ws[i] = W[i];
    int nbase = blockIdx.x * NODES;
    if (bnin) {
        __syncthreads();  // scale/shift ready
        for (int i = tid; i < NODES * 64; i += 256) {
            int n = i >> 6, k = i & 63;
            float v = 0.f;
            if (nbase + n < NN)
                v = fmaxf(fmaf(in[(nbase + n) * 64 + k], scale[k], shift[k]), 0.f);
            xs[n * XP + k] = v;
        }
    } else {
        for (int i = tid; i < NODES * 64; i += 256) {
            int n = i >> 6, k = i & 63;
            xs[n * XP + k] = (nbase + n < NN) ? in[(nbase + n) * 64 + k] : 0.f;
        }
    }
    __syncthreads();

    int ng = tid & (NG - 1);
    int cg = tid / NG;
    float4 acc[4];
#pragma unroll
    for (int r = 0; r < 4; r++) acc[r] = make_float4(0.f, 0.f, 0.f, 0.f);

#pragma unroll
    for (int kt = 0; kt < 16; kt++) {
        // 4 W rows (warp-broadcast LDS.128)
        float4 w0 = *reinterpret_cast<const float4*>(&Ws[(kt * 4 + 0) * FOUT + cg * 4]);
        float4 w1 = *reinterpret_cast<const float4*>(&Ws[(kt * 4 + 1) * FOUT + cg * 4]);
        float4 w2 = *reinterpret_cast<const float4*>(&Ws[(kt * 4 + 2) * FOUT + cg * 4]);
        float4 w3 = *reinterpret_cast<const float4*>(&Ws[(kt * 4 + 3) * FOUT + cg * 4]);
#pragma unroll
        for (int r = 0; r < 4; r++) {
            float4 xv = *reinterpret_cast<const float4*>(&xs[(ng + r * NG) * XP + kt * 4]);
            acc[r].x = fmaf(xv.x, w0.x, acc[r].x);
            acc[r].y = fmaf(xv.x, w0.y, acc[r].y);
            acc[r].z = fmaf(xv.x, w0.z, acc[r].z);
            acc[r].w = fmaf(xv.x, w0.w, acc[r].w);
            acc[r].x = fmaf(xv.y, w1.x, acc[r].x);
            acc[r].y = fmaf(xv.y, w1.y, acc[r].y);
            acc[r].z = fmaf(xv.y, w1.z, acc[r].z);
            acc[r].w = fmaf(xv.y, w1.w, acc[r].w);
            acc[r].x = fmaf(xv.z, w2.x, acc[r].x);
            acc[r].y = fmaf(xv.z, w2.y, acc[r].y);
            acc[r].z = fmaf(xv.z, w2.z, acc[r].z);
            acc[r].w = fmaf(xv.z, w2.w, acc[r].w);
            acc[r].x = fmaf(xv.w, w3.x, acc[r].x);
            acc[r].y = fmaf(xv.w, w3.y, acc[r].y);
            acc[r].z = fmaf(xv.w, w3.z, acc[r].z);
            acc[r].w = fmaf(xv.w, w3.w, acc[r].w);
        }
    }
#pragma unroll
    for (int r = 0; r < 4; r++) {
        int n = nbase + ng + r * NG;
        if (n < NN) {
            __half2 lo = __floats2half2_rn(acc[r].x, acc[r].y);
            __half2 hi = __floats2half2_rn(acc[r].z, acc[r].w);
            uint2 pk = make_uint2(*(unsigned*)&lo, *(unsigned*)&hi);
            *reinterpret_cast<uint2*>(&d_h16[n * FOUT + cg * 4]) = pk;
        }
    }
}

// ---------------- CSR gather: one warp per dst node, fp16 h ------------------
// agg[d] = dinv[d]*( sum_e dinv[s] h[s] + dinv[d] h[d] ) + b
template <int F>
__global__ void gather_k(const float* __restrict__ bias) {
    int d = (blockIdx.x * blockDim.x + threadIdx.x) >> 5;
    int lane = threadIdx.x & 31;
    if (d >= NN) return;
    int e = __ldg(&d_rowptr[d]), end = __ldg(&d_rowptr[d + 1]);

    if (F == 64) {
        const __half2* hp = (const __half2*)d_h16;  // 32 half2 per node row
        float ax = 0.f, ay = 0.f;
        for (; e + 4 <= end; e += 4) {
            int2 p0 = d_csr[e],     p1 = d_csr[e + 1];
            int2 p2 = d_csr[e + 2], p3 = d_csr[e + 3];
            float2 h0 = __half22float2(hp[p0.x * 32 + lane]);
            float2 h1 = __half22float2(hp[p1.x * 32 + lane]);
            float2 h2 = __half22float2(hp[p2.x * 32 + lane]);
            float2 h3 = __half22float2(hp[p3.x * 32 + lane]);
            float w0 = __int_as_float(p0.y), w1 = __int_as_float(p1.y);
            float w2 = __int_as_float(p2.y), w3 = __int_as_float(p3.y);
            ax = fmaf(w0, h0.x, fmaf(w1, h1.x, fmaf(w2, h2.x, fmaf(w3, h3.x, ax))));
            ay = fmaf(w0, h0.y, fmaf(w1, h1.y, fmaf(w2, h2.y, fmaf(w3, h3.y, ay))));
        }
        for (; e < end; e++) {
            int2 p = d_csr[e];
            float2 hv = __half22float2(hp[p.x * 32 + lane]);
            float w = __int_as_float(p.y);
            ax = fmaf(w, hv.x, ax);
            ay = fmaf(w, hv.y, ay);
        }
        float dd = d_deg[d];
        float2 hd = __half22float2(hp[d * 32 + lane]);
        float2 o;
        o.x = fmaf(fmaf(dd, hd.x, ax), dd, bias[2 * lane]);
        o.y = fmaf(fmaf(dd, hd.y, ay), dd, bias[2 * lane + 1]);
        *reinterpret_cast<float2*>(&d_agg[d * 64 + lane * 2]) = o;
    } else {
        const __half* hs = d_h16;  // 32 half per node row
        float a = 0.f;
        for (; e + 4 <= end; e += 4) {
            int2 p0 = d_csr[e],     p1 = d_csr[e + 1];
            int2 p2 = d_csr[e + 2], p3 = d_csr[e + 3];
            float h0 = __half2float(hs[p0.x * 32 + lane]);
            float h1 = __half2float(hs[p1.x * 32 + lane]);
            float h2 = __half2float(hs[p2.x * 32 + lane]);
            float h3 = __half2float(hs[p3.x * 32 + lane]);
            a = fmaf(__int_as_float(p0.y), h0, fmaf(__int_as_float(p1.y), h1,
                fmaf(__int_as_float(p2.y), h2, fmaf(__int_as_float(p3.y), h3, a))));
        }
        for (; e < end; e++) {
            int2 p = d_csr[e];
            a = fmaf(__int_as_float(p.y), __half2float(hs[p.x * 32 + lane]), a);
        }
        float dd = d_deg[d];
        float hd = __half2float(hs[d * 32 + lane]);
        d_agg[d * 32 + lane] = fmaf(fmaf(dd, hd, a), dd, bias[lane]);
    }
}

// ---------------- BN stats (streaming read of d_agg) -------------------------
template <int FOUT>
__global__ void bn_stats(float* __restrict__ bnout) {
    int t = blockIdx.x * blockDim.x + threadIdx.x;  // 65536 threads
    int c = t % FOUT;
    int r = t / FOUT;
    const int step = (256 * 256) / FOUT;
    float s = 0.f, ss = 0.f;
#pragma unroll 4
    for (; r < NN; r += step) {
        float v = d_agg[r * FOUT + c];
        s += v;
        ss = fmaf(v, v, ss);
    }
    atomicAdd(&bnout[c], s);
    atomicAdd(&bnout[64 + c], ss);
}

// ---------------- pooling (fused final BN+ReLU) + classifier -----------------
__global__ void pool_add(const int* __restrict__ batch, const float* __restrict__ bnin,
                         const float* __restrict__ g, const float* __restrict__ be) {
    __shared__ float scale[32], shift[32];
    int tid = threadIdx.x;
    if (tid < 32) {
        const float invn = 1.f / (float)NN;
        float mu = bnin[tid] * invn;
        float var = bnin[64 + tid] * invn - mu * mu;
        float s = g[tid] * rsqrtf(var + 1e-5f);
        scale[tid] = s;
        shift[tid] = fmaf(-mu, s, be[tid]);
    }
    __syncthreads();
    int i = blockIdx.x * blockDim.x + tid;
    if (i >= NN * 8) return;
    int n = i >> 3, c = i & 7;
    int g_ = batch[n];
    const float4 v = *reinterpret_cast<const float4*>(&d_agg[n * 32 + c * 4]);
    int cb = c * 4;
    float a  = fmaxf(fmaf(v.x, scale[cb],     shift[cb]),     0.f);
    float b  = fmaxf(fmaf(v.y, scale[cb + 1], shift[cb + 1]), 0.f);
    float c2 = fmaxf(fmaf(v.z, scale[cb + 2], shift[cb + 2]), 0.f);
    float d  = fmaxf(fmaf(v.w, scale[cb + 3], shift[cb + 3]), 0.f);
    red4(&d_pool[g_ * 32 + cb], a, b, c2, d);
    if (c == 0) atomicAdd(&d_cnt[g_], 1.f);
}

__global__ void classify(const float* __restrict__ Wl, const float* __restrict__ bl,
                         float* __restrict__ out) {
    int g = blockIdx.x * blockDim.x + threadIdx.x;
    if (g >= GG) return;
    float inv = 1.f / fmaxf(d_cnt[g], 1.f);
    float lo[CC];
#pragma unroll
    for (int c = 0; c < CC; c++) lo[c] = bl[c];
#pragma unroll
    for (int k = 0; k < 32; k++) {
        float p = d_pool[g * 32 + k] * inv;
#pragma unroll
        for (int c = 0; c < CC; c++) lo[c] = fmaf(p, Wl[k * CC + c], lo[c]);
    }
    float m = lo[0];
#pragma unroll
    for (int c = 1; c < CC; c++) m = fmaxf(m, lo[c]);
    float s = 0.f;
#pragma unroll
    for (int c = 0; c < CC; c++) { lo[c] = expf(lo[c] - m); s += lo[c]; }
    float is = 1.f / s;
#pragma unroll
    for (int c = 0; c < CC; c++) out[g * CC + c] = lo[c] * is;
}

// ---------------- launch -----------------------------------------------------
extern "C" void kernel_launch(void* const* d_in, const int* in_sizes, int n_in,
                              void* d_out, int out_size) {
    const float* x   = (const float*)d_in[0];
    const int* esrc  = (const int*)d_in[1];
    const int* edst  = (const int*)d_in[2];
    const int* batch = (const int*)d_in[3];
    const float* W1 = (const float*)d_in[4];   const float* b1 = (const float*)d_in[5];
    const float* W2 = (const float*)d_in[6];   const float* b2 = (const float*)d_in[7];
    const float* W4 = (const float*)d_in[8];   const float* b4 = (const float*)d_in[9];
    const float* W3 = (const float*)d_in[10];  const float* b3 = (const float*)d_in[11];
    const float* g1 = (const float*)d_in[12];  const float* be1 = (const float*)d_in[13];
    const float* g2 = (const float*)d_in[14];  const float* be2 = (const float*)d_in[15];
    const float* g4 = (const float*)d_in[16];  const float* be4 = (const float*)d_in[17];
    const float* g3 = (const float*)d_in[18];  const float* be3 = (const float*)d_in[19];
    const float* Wl = (const float*)d_in[20];  const float* bl = (const float*)d_in[21];
    float* out = (float*)d_out;

    float* bn0;  cudaGetSymbolAddress((void**)&bn0, d_bnbuf);
    float* bn1 = bn0 + 128;
    void* p_cnts; cudaGetSymbolAddress(&p_cnts, d_cnts);
    void* p_pool; cudaGetSymbolAddress(&p_pool, d_pool);
    void* p_cnt;  cudaGetSymbolAddress(&p_cnt, d_cnt);

    // setup: degrees + CSR by dst (zeroing via capturable memsets)
    cudaMemsetAsync(p_cnts, 0, NN * sizeof(int), 0);
    cudaMemsetAsync(p_pool, 0, GG * 32 * sizeof(float), 0);
    cudaMemsetAsync(p_cnt, 0, GG * sizeof(float), 0);
    count_deg<<<(EE + 255) / 256, 256>>>(edst);
    scan_bsum<<<NB, 256>>>();
    scan_final<<<NB, 256>>>();
    fill_csr<<<(EE + 255) / 256, 256>>>(esrc, edst);

    // layer 1 (conv1): x -> 64 ; stats -> bn0
    gemm_k<64><<<(NN + 63) / 64, 256>>>(x, W1, nullptr, nullptr, nullptr, bn0);
    gather_k<64><<<(NN * 32 + 255) / 256, 256>>>(b1);
    bn_stats<64><<<256, 256>>>(bn0);

    // layer 2 (conv2): BN1 -> 64 ; stats -> bn1
    gemm_k<64><<<(NN + 63) / 64, 256>>>(nullptr, W2, bn0, g1, be1, bn1);
    gather_k<64><<<(NN * 32 + 255) / 256, 256>>>(b2);
    bn_stats<64><<<256, 256>>>(bn1);

    // layer 3 (conv4): BN2 -> 64 ; stats -> bn0
    gemm_k<64><<<(NN + 63) / 64, 256>>>(nullptr, W4, bn1, g2, be2, bn0);
    gather_k<64><<<(NN * 32 + 255) / 256, 256>>>(b4);
    bn_stats<64><<<256, 256>>>(bn0);

    // layer 4 (conv3): BN4 -> 32 ; stats -> bn1
    gemm_k<32><<<(NN + 127) / 128, 256>>>(nullptr, W3, bn0, g4, be4, bn1);
    gather_k<32><<<(NN * 32 + 255) / 256, 256>>>(b3);
    bn_stats<32><<<256, 256>>>(bn1);

    // pool (fused BN3+ReLU) + classifier
    pool_add<<<(NN * 8 + 255) / 256, 256>>>(batch, bn1, g3, be3);
    classify<<<1, 256>>>(Wl, bl, out);
}

// round 14
// speedup vs baseline: 1.0833x; 1.0833x over previous
#include <cuda_runtime.h>
#include <cuda_fp16.h>

#define NN 50000
#define EE 1200000
#define GG 256
#define CC 10
#define NB 196   // scan blocks: ceil(NN/256)

// ---------------- scratch (device globals; no allocation allowed) ----------
__device__ __align__(16) float d_deg[NN];        // dinv
__device__ __align__(16) int   d_cnts[NN];       // in-degree (int)
__device__ __align__(16) int   d_rowptr[NN + 1];
__device__ __align__(16) int   d_cur[NN];        // fill cursors
__device__ __align__(16) int   d_bsum[NB];
__device__ __align__(16) int   d_csr[EE];        // src only (h is pre-scaled by dinv)
__device__ __align__(16) __half d_h16[NN * 64];  // dinv[n] * (x@W)[n]  (fp16)
__device__ __align__(16) float d_agg[NN * 64];   // aggregated (pre-BN, fp32)
__device__ __align__(16) float d_bnbuf[2][128];  // BN sums, double-buffered
__device__ __align__(16) float d_pool[GG * 32];
__device__ __align__(16) float d_cnt[GG];

__device__ __forceinline__ void red4(float* p, float a, float b, float c, float d) {
    asm volatile("red.global.add.v4.f32 [%0], {%1,%2,%3,%4};"
                 :: "l"(p), "f"(a), "f"(b), "f"(c), "f"(d) : "memory");
}

// ---------------- setup ------------------------------------------------------
__global__ void count_deg(const int* __restrict__ dst) {
    int i = blockIdx.x * blockDim.x + threadIdx.x;
    if (i < EE) atomicAdd(&d_cnts[dst[i]], 1);
}

// per-256-block degree sums (for scan) + dinv
__global__ void scan_bsum() {
    int i = blockIdx.x * 256 + threadIdx.x;
    int v = (i < NN) ? d_cnts[i] : 0;
    if (i < NN) d_deg[i] = rsqrtf((float)v + 1.f);
#pragma unroll
    for (int o = 16; o > 0; o >>= 1) v += __shfl_down_sync(0xffffffffu, v, o);
    __shared__ int sh[8];
    if ((threadIdx.x & 31) == 0) sh[threadIdx.x >> 5] = v;
    __syncthreads();
    if (threadIdx.x == 0) {
        int s = 0;
#pragma unroll
        for (int w = 0; w < 8; w++) s += sh[w];
        d_bsum[blockIdx.x] = s;
    }
}

// exclusive scan -> rowptr + cursors; each block redundantly reduces its d_bsum prefix
__global__ void scan_final() {
    __shared__ int sh[256];
    __shared__ int wsum[8];
    int tid = threadIdx.x;
    int pv = (tid < blockIdx.x) ? d_bsum[tid] : 0;   // NB=196 < 256
#pragma unroll
    for (int o = 16; o > 0; o >>= 1) pv += __shfl_down_sync(0xffffffffu, pv, o);
    if ((tid & 31) == 0) wsum[tid >> 5] = pv;
    __syncthreads();
    int boff = 0;
#pragma unroll
    for (int w = 0; w < 8; w++) boff += wsum[w];

    int i = blockIdx.x * 256 + tid;
    int v = (i < NN) ? d_cnts[i] : 0;
    sh[tid] = v;
    __syncthreads();
#pragma unroll
    for (int o = 1; o < 256; o <<= 1) {
        int t = (tid >= o) ? sh[tid - o] : 0;
        __syncthreads();
        sh[tid] += t;
        __syncthreads();
    }
    if (i < NN) {
        int excl = sh[tid] - v + boff;
        d_rowptr[i] = excl;
        d_cur[i] = excl;
    }
    if (blockIdx.x == NB - 1 && tid == 255) d_rowptr[NN] = boff + sh[255];
}

// src-only CSR fill: atomic cursor + 4B scattered store (no dinv lookup)
__global__ void fill_csr(const int* __restrict__ src, const int* __restrict__ dst) {
    int e = blockIdx.x * blockDim.x + threadIdx.x;
    if (e >= EE) return;
    int pos = atomicAdd(&d_cur[dst[e]], 1);
    d_csr[pos] = src[e];
}

// ---------------- register-tiled GEMM, fused BN+ReLU on input ---------------
// h16 = dinv * (relu(BN(in)) @ W) ; block 0 zeroes bnzero.
template <int FOUT>
__global__ void gemm_k(const float* __restrict__ xin, const float* __restrict__ W,
                       const float* __restrict__ bnin, const float* __restrict__ g,
                       const float* __restrict__ be, float* __restrict__ bnzero) {
    constexpr int CG = FOUT / 4;      // col groups   (16 or 8)
    constexpr int NG = 256 / CG;      // node groups  (16 or 32)
    constexpr int NODES = NG * 4;     // 64 or 128 nodes per block
    __shared__ float Ws[64 * FOUT];
    __shared__ float xs[NODES * 65];  // +1 float pad per row
    __shared__ float scale[64], shift[64];

    const float* in = xin ? xin : d_agg;
    int tid = threadIdx.x;
    if (bnin && tid < 64) {
        const float invn = 1.f / (float)NN;
        float mu = bnin[tid] * invn;
        float var = bnin[64 + tid] * invn - mu * mu;
        float s = g[tid] * rsqrtf(var + 1e-5f);
        scale[tid] = s;
        shift[tid] = fmaf(-mu, s, be[tid]);
    }
    if (blockIdx.x == 0 && tid < 128) bnzero[tid] = 0.f;
    for (int i = tid; i < 64 * FOUT; i += 256) Ws[i] = W[i];
    int nbase = blockIdx.x * NODES;
    if (bnin) {
        __syncthreads();  // scale/shift ready
        for (int i = tid; i < NODES * 64; i += 256) {
            int n = i >> 6, k = i & 63;
            float v = 0.f;
            if (nbase + n < NN)
                v = fmaxf(fmaf(in[(nbase + n) * 64 + k], scale[k], shift[k]), 0.f);
            xs[n * 65 + k] = v;
        }
    } else {
        for (int i = tid; i < NODES * 64; i += 256) {
            int n = i >> 6, k = i & 63;
            xs[n * 65 + k] = (nbase + n < NN) ? in[(nbase + n) * 64 + k] : 0.f;
        }
    }
    __syncthreads();

    int ng = tid & (NG - 1);
    int cg = tid / NG;
    float4 acc[4];
#pragma unroll
    for (int r = 0; r < 4; r++) acc[r] = make_float4(0.f, 0.f, 0.f, 0.f);

#pragma unroll
    for (int k = 0; k < 64; k++) {
        float4 w = *reinterpret_cast<const float4*>(&Ws[k * FOUT + cg * 4]);
#pragma unroll
        for (int r = 0; r < 4; r++) {
            float xv = xs[(ng + r * NG) * 65 + k];
            acc[r].x = fmaf(xv, w.x, acc[r].x);
            acc[r].y = fmaf(xv, w.y, acc[r].y);
            acc[r].z = fmaf(xv, w.z, acc[r].z);
            acc[r].w = fmaf(xv, w.w, acc[r].w);
        }
    }
#pragma unroll
    for (int r = 0; r < 4; r++) {
        int n = nbase + ng + r * NG;
        if (n < NN) {
            float di = d_deg[n];
            __half2 lo = __floats2half2_rn(acc[r].x * di, acc[r].y * di);
            __half2 hi = __floats2half2_rn(acc[r].z * di, acc[r].w * di);
            uint2 pk = make_uint2(*(unsigned*)&lo, *(unsigned*)&hi);
            *reinterpret_cast<uint2*>(&d_h16[n * FOUT + cg * 4]) = pk;
        }
    }
}

// ---------------- CSR gather: one warp per dst node, weight-free -------------
// agg[d] = dinv[d]*( sum_nbr h'[s] + h'[d] ) + b
template <int F>
__global__ void gather_k(const float* __restrict__ bias) {
    int d = (blockIdx.x * blockDim.x + threadIdx.x) >> 5;
    int lane = threadIdx.x & 31;
    if (d >= NN) return;
    int e = __ldg(&d_rowptr[d]), end = __ldg(&d_rowptr[d + 1]);

    if (F == 64) {
        const __half2* hp = (const __half2*)d_h16;  // 32 half2 per node row
        float ax = 0.f, ay = 0.f;
        for (; e + 4 <= end; e += 4) {
            int s0 = d_csr[e],     s1 = d_csr[e + 1];
            int s2 = d_csr[e + 2], s3 = d_csr[e + 3];
            float2 h0 = __half22float2(hp[s0 * 32 + lane]);
            float2 h1 = __half22float2(hp[s1 * 32 + lane]);
            float2 h2 = __half22float2(hp[s2 * 32 + lane]);
            float2 h3 = __half22float2(hp[s3 * 32 + lane]);
            ax += (h0.x + h1.x) + (h2.x + h3.x);
            ay += (h0.y + h1.y) + (h2.y + h3.y);
        }
        for (; e < end; e++) {
            float2 hv = __half22float2(hp[d_csr[e] * 32 + lane]);
            ax += hv.x;
            ay += hv.y;
        }
        float dd = d_deg[d];
        float2 hd = __half22float2(hp[d * 32 + lane]);
        float2 o;
        o.x = fmaf(ax + hd.x, dd, bias[2 * lane]);
        o.y = fmaf(ay + hd.y, dd, bias[2 * lane + 1]);
        *reinterpret_cast<float2*>(&d_agg[d * 64 + lane * 2]) = o;
    } else {
        const __half* hs = d_h16;  // 32 half per node row
        float a = 0.f;
        for (; e + 4 <= end; e += 4) {
            int s0 = d_csr[e],     s1 = d_csr[e + 1];
            int s2 = d_csr[e + 2], s3 = d_csr[e + 3];
            float h0 = __half2float(hs[s0 * 32 + lane]);
            float h1 = __half2float(hs[s1 * 32 + lane]);
            float h2 = __half2float(hs[s2 * 32 + lane]);
            float h3 = __half2float(hs[s3 * 32 + lane]);
            a += (h0 + h1) + (h2 + h3);
        }
        for (; e < end; e++) a += __half2float(hs[d_csr[e] * 32 + lane]);
        float dd = d_deg[d];
        float hd = __half2float(hs[d * 32 + lane]);
        d_agg[d * 32 + lane] = fmaf(a + hd, dd, bias[lane]);
    }
}

// ---------------- BN stats (streaming read of d_agg) -------------------------
template <int FOUT>
__global__ void bn_stats(float* __restrict__ bnout) {
    int t = blockIdx.x * blockDim.x + threadIdx.x;  // 65536 threads
    int c = t % FOUT;
    int r = t / FOUT;
    const int step = (256 * 256) / FOUT;
    float s = 0.f, ss = 0.f;
    for (; r < NN; r += step) {
        float v = d_agg[r * FOUT + c];
        s += v;
        ss = fmaf(v, v, ss);
    }
    atomicAdd(&bnout[c], s);
    atomicAdd(&bnout[64 + c], ss);
}

// ---------------- pooling (fused final BN+ReLU) + classifier -----------------
__global__ void pool_add(const int* __restrict__ batch, const float* __restrict__ bnin,
                         const float* __restrict__ g, const float* __restrict__ be) {
    __shared__ float scale[32], shift[32];
    int tid = threadIdx.x;
    if (tid < 32) {
        const float invn = 1.f / (float)NN;
        float mu = bnin[tid] * invn;
        float var = bnin[64 + tid] * invn - mu * mu;
        float s = g[tid] * rsqrtf(var + 1e-5f);
        scale[tid] = s;
        shift[tid] = fmaf(-mu, s, be[tid]);
    }
    __syncthreads();
    int i = blockIdx.x * blockDim.x + tid;
    if (i >= NN * 8) return;
    int n = i >> 3, c = i & 7;
    int g_ = batch[n];
    const float4 v = *reinterpret_cast<const float4*>(&d_agg[n * 32 + c * 4]);
    int cb = c * 4;
    float a  = fmaxf(fmaf(v.x, scale[cb],     shift[cb]),     0.f);
    float b  = fmaxf(fmaf(v.y, scale[cb + 1], shift[cb + 1]), 0.f);
    float c2 = fmaxf(fmaf(v.z, scale[cb + 2], shift[cb + 2]), 0.f);
    float d  = fmaxf(fmaf(v.w, scale[cb + 3], shift[cb + 3]), 0.f);
    red4(&d_pool[g_ * 32 + cb], a, b, c2, d);
    if (c == 0) atomicAdd(&d_cnt[g_], 1.f);
}

__global__ void classify(const float* __restrict__ Wl, const float* __restrict__ bl,
                         float* __restrict__ out) {
    int g = blockIdx.x * blockDim.x + threadIdx.x;
    if (g >= GG) return;
    float inv = 1.f / fmaxf(d_cnt[g], 1.f);
    float lo[CC];
#pragma unroll
    for (int c = 0; c < CC; c++) lo[c] = bl[c];
#pragma unroll
    for (int k = 0; k < 32; k++) {
        float p = d_pool[g * 32 + k] * inv;
#pragma unroll
        for (int c = 0; c < CC; c++) lo[c] = fmaf(p, Wl[k * CC + c], lo[c]);
    }
    float m = lo[0];
#pragma unroll
    for (int c = 1; c < CC; c++) m = fmaxf(m, lo[c]);
    float s = 0.f;
#pragma unroll
    for (int c = 0; c < CC; c++) { lo[c] = expf(lo[c] - m); s += lo[c]; }
    float is = 1.f / s;
#pragma unroll
    for (int c = 0; c < CC; c++) out[g * CC + c] = lo[c] * is;
}

// ---------------- launch -----------------------------------------------------
extern "C" void kernel_launch(void* const* d_in, const int* in_sizes, int n_in,
                              void* d_out, int out_size) {
    const float* x   = (const float*)d_in[0];
    const int* esrc  = (const int*)d_in[1];
    const int* edst  = (const int*)d_in[2];
    const int* batch = (const int*)d_in[3];
    const float* W1 = (const float*)d_in[4];   const float* b1 = (const float*)d_in[5];
    const float* W2 = (const float*)d_in[6];   const float* b2 = (const float*)d_in[7];
    const float* W4 = (const float*)d_in[8];   const float* b4 = (const float*)d_in[9];
    const float* W3 = (const float*)d_in[10];  const float* b3 = (const float*)d_in[11];
    const float* g1 = (const float*)d_in[12];  const float* be1 = (const float*)d_in[13];
    const float* g2 = (const float*)d_in[14];  const float* be2 = (const float*)d_in[15];
    const float* g4 = (const float*)d_in[16];  const float* be4 = (const float*)d_in[17];
    const float* g3 = (const float*)d_in[18];  const float* be3 = (const float*)d_in[19];
    const float* Wl = (const float*)d_in[20];  const float* bl = (const float*)d_in[21];
    float* out = (float*)d_out;

    float* bn0;  cudaGetSymbolAddress((void**)&bn0, d_bnbuf);
    float* bn1 = bn0 + 128;
    void* p_cnts; cudaGetSymbolAddress(&p_cnts, d_cnts);
    void* p_pool; cudaGetSymbolAddress(&p_pool, d_pool);
    void* p_cnt;  cudaGetSymbolAddress(&p_cnt, d_cnt);

    // setup: degrees + CSR by dst (zeroing via capturable memsets)
    cudaMemsetAsync(p_cnts, 0, NN * sizeof(int), 0);
    cudaMemsetAsync(p_pool, 0, GG * 32 * sizeof(float), 0);
    cudaMemsetAsync(p_cnt, 0, GG * sizeof(float), 0);
    count_deg<<<(EE + 255) / 256, 256>>>(edst);
    scan_bsum<<<NB, 256>>>();
    scan_final<<<NB, 256>>>();
    fill_csr<<<(EE + 255) / 256, 256>>>(esrc, edst);

    // layer 1 (conv1): x -> 64 ; stats -> bn0
    gemm_k<64><<<(NN + 63) / 64, 256>>>(x, W1, nullptr, nullptr, nullptr, bn0);
    gather_k<64><<<(NN * 32 + 255) / 256, 256>>>(b1);
    bn_stats<64><<<256, 256>>>(bn0);

    // layer 2 (conv2): BN1 -> 64 ; stats -> bn1
    gemm_k<64><<<(NN + 63) / 64, 256>>>(nullptr, W2, bn0, g1, be1, bn1);
    gather_k<64><<<(NN * 32 + 255) / 256, 256>>>(b2);
    bn_stats<64><<<256, 256>>>(bn1);

    // layer 3 (conv4): BN2 -> 64 ; stats -> bn0
    gemm_k<64><<<(NN + 63) / 64, 256>>>(nullptr, W4, bn1, g2, be2, bn0);
    gather_k<64><<<(NN * 32 + 255) / 256, 256>>>(b4);
    bn_stats<64><<<256, 256>>>(bn0);

    // layer 4 (conv3): BN4 -> 32 ; stats -> bn1
    gemm_k<32><<<(NN + 127) / 128, 256>>>(nullptr, W3, bn0, g4, be4, bn1);
    gather_k<32><<<(NN * 32 + 255) / 256, 256>>>(b3);
    bn_stats<32><<<256, 256>>>(bn1);

    // pool (fused BN3+ReLU) + classifier
    pool_add<<<(NN * 8 + 255) / 256, 256>>>(batch, bn1, g3, be3);
    classify<<<1, 256>>>(Wl, bl, out);
}

// round 15
// speedup vs baseline: 1.1000x; 1.0154x over previous
#include <cuda_runtime.h>
#include <cuda_fp16.h>

#define NN 50000
#define EE 1200000
#define GG 256
#define CC 10
#define NB 196   // scan blocks: ceil(NN/256)

// ---------------- scratch (device globals; no allocation allowed) ----------
__device__ __align__(16) float d_deg[NN];        // dinv
__device__ __align__(16) int   d_cnts[NN];       // in-degree (int)
__device__ __align__(16) int   d_rowptr[NN + 1];
__device__ __align__(16) int   d_cur[NN];        // fill cursors
__device__ __align__(16) int   d_bsum[NB];
__device__ __align__(16) int   d_csr[EE];        // src only (h is pre-scaled by dinv)
__device__ __align__(16) __half d_h16[NN * 64];  // dinv[n] * (x@W)[n]  (fp16)
__device__ __align__(16) float d_agg[NN * 64];   // aggregated (pre-BN, fp32)
__device__ __align__(16) float d_bnbuf[2][128];  // BN sums, double-buffered
__device__ __align__(16) float d_pool[GG * 32];
__device__ __align__(16) float d_cnt[GG];

__device__ __forceinline__ void red4(float* p, float a, float b, float c, float d) {
    asm volatile("red.global.add.v4.f32 [%0], {%1,%2,%3,%4};"
                 :: "l"(p), "f"(a), "f"(b), "f"(c), "f"(d) : "memory");
}

// ---------------- setup ------------------------------------------------------
__global__ void count_deg(const int* __restrict__ dst) {
    int i = blockIdx.x * blockDim.x + threadIdx.x;
    if (i < EE) atomicAdd(&d_cnts[dst[i]], 1);
}

// per-256-block degree sums (for scan) + dinv
__global__ void scan_bsum() {
    int i = blockIdx.x * 256 + threadIdx.x;
    int v = (i < NN) ? d_cnts[i] : 0;
    if (i < NN) d_deg[i] = rsqrtf((float)v + 1.f);
#pragma unroll
    for (int o = 16; o > 0; o >>= 1) v += __shfl_down_sync(0xffffffffu, v, o);
    __shared__ int sh[8];
    if ((threadIdx.x & 31) == 0) sh[threadIdx.x >> 5] = v;
    __syncthreads();
    if (threadIdx.x == 0) {
        int s = 0;
#pragma unroll
        for (int w = 0; w < 8; w++) s += sh[w];
        d_bsum[blockIdx.x] = s;
    }
}

// exclusive scan -> rowptr + cursors; each block redundantly reduces its d_bsum prefix
__global__ void scan_final() {
    __shared__ int sh[256];
    __shared__ int wsum[8];
    int tid = threadIdx.x;
    int pv = (tid < blockIdx.x) ? d_bsum[tid] : 0;   // NB=196 < 256
#pragma unroll
    for (int o = 16; o > 0; o >>= 1) pv += __shfl_down_sync(0xffffffffu, pv, o);
    if ((tid & 31) == 0) wsum[tid >> 5] = pv;
    __syncthreads();
    int boff = 0;
#pragma unroll
    for (int w = 0; w < 8; w++) boff += wsum[w];

    int i = blockIdx.x * 256 + tid;
    int v = (i < NN) ? d_cnts[i] : 0;
    sh[tid] = v;
    __syncthreads();
#pragma unroll
    for (int o = 1; o < 256; o <<= 1) {
        int t = (tid >= o) ? sh[tid - o] : 0;
        __syncthreads();
        sh[tid] += t;
        __syncthreads();
    }
    if (i < NN) {
        int excl = sh[tid] - v + boff;
        d_rowptr[i] = excl;
        d_cur[i] = excl;
    }
    if (blockIdx.x == NB - 1 && tid == 255) d_rowptr[NN] = boff + sh[255];
}

// src-only CSR fill: atomic cursor + 4B scattered store
__global__ void fill_csr(const int* __restrict__ src, const int* __restrict__ dst) {
    int e = blockIdx.x * blockDim.x + threadIdx.x;
    if (e >= EE) return;
    int pos = atomicAdd(&d_cur[dst[e]], 1);
    d_csr[pos] = src[e];
}

// ---------------- register-tiled GEMM, fused BN+ReLU on input ---------------
// h16 = dinv * (relu(BN(in)) @ W) ; block 0 zeroes bnzero.
template <int FOUT>
__global__ void gemm_k(const float* __restrict__ xin, const float* __restrict__ W,
                       const float* __restrict__ bnin, const float* __restrict__ g,
                       const float* __restrict__ be, float* __restrict__ bnzero) {
    constexpr int CG = FOUT / 4;      // col groups   (16 or 8)
    constexpr int NG = 256 / CG;      // node groups  (16 or 32)
    constexpr int NODES = NG * 4;     // 64 or 128 nodes per block
    __shared__ float Ws[64 * FOUT];
    __shared__ float xs[NODES * 65];  // +1 float pad per row
    __shared__ float scale[64], shift[64];

    const float* in = xin ? xin : d_agg;
    int tid = threadIdx.x;
    if (bnin && tid < 64) {
        const float invn = 1.f / (float)NN;
        float mu = bnin[tid] * invn;
        float var = bnin[64 + tid] * invn - mu * mu;
        float s = g[tid] * rsqrtf(var + 1e-5f);
        scale[tid] = s;
        shift[tid] = fmaf(-mu, s, be[tid]);
    }
    if (blockIdx.x == 0 && tid < 128) bnzero[tid] = 0.f;
    for (int i = tid; i < 64 * FOUT; i += 256) Ws[i] = W[i];
    int nbase = blockIdx.x * NODES;
    if (bnin) {
        __syncthreads();  // scale/shift ready
        for (int i = tid; i < NODES * 64; i += 256) {
            int n = i >> 6, k = i & 63;
            float v = 0.f;
            if (nbase + n < NN)
                v = fmaxf(fmaf(in[(nbase + n) * 64 + k], scale[k], shift[k]), 0.f);
            xs[n * 65 + k] = v;
        }
    } else {
        for (int i = tid; i < NODES * 64; i += 256) {
            int n = i >> 6, k = i & 63;
            xs[n * 65 + k] = (nbase + n < NN) ? in[(nbase + n) * 64 + k] : 0.f;
        }
    }
    __syncthreads();

    int ng = tid & (NG - 1);
    int cg = tid / NG;
    float4 acc[4];
#pragma unroll
    for (int r = 0; r < 4; r++) acc[r] = make_float4(0.f, 0.f, 0.f, 0.f);

#pragma unroll
    for (int k = 0; k < 64; k++) {
        float4 w = *reinterpret_cast<const float4*>(&Ws[k * FOUT + cg * 4]);
#pragma unroll
        for (int r = 0; r < 4; r++) {
            float xv = xs[(ng + r * NG) * 65 + k];
            acc[r].x = fmaf(xv, w.x, acc[r].x);
            acc[r].y = fmaf(xv, w.y, acc[r].y);
            acc[r].z = fmaf(xv, w.z, acc[r].z);
            acc[r].w = fmaf(xv, w.w, acc[r].w);
        }
    }
#pragma unroll
    for (int r = 0; r < 4; r++) {
        int n = nbase + ng + r * NG;
        if (n < NN) {
            float di = d_deg[n];
            __half2 lo = __floats2half2_rn(acc[r].x * di, acc[r].y * di);
            __half2 hi = __floats2half2_rn(acc[r].z * di, acc[r].w * di);
            uint2 pk = make_uint2(*(unsigned*)&lo, *(unsigned*)&hi);
            *reinterpret_cast<uint2*>(&d_h16[n * FOUT + cg * 4]) = pk;
        }
    }
}

// ---------------- CSR gather: one warp per dst node ---------------------------
// Lane-parallel index prefetch (one coalesced load per 32 edges) + shfl
// broadcast; h-row loads then have no L2 index dependency.
// agg[d] = dinv[d]*( sum_nbr h'[s] + h'[d] ) + b
template <int F>
__global__ void gather_k(const float* __restrict__ bias) {
    int d = (blockIdx.x * blockDim.x + threadIdx.x) >> 5;
    int lane = threadIdx.x & 31;
    if (d >= NN) return;
    int e = __ldg(&d_rowptr[d]), end = __ldg(&d_rowptr[d + 1]);

    if (F == 64) {
        const __half2* hp = (const __half2*)d_h16;  // 32 half2 per node row
        float ax = 0.f, ay = 0.f;
        while (e < end) {
            int cnt = min(32, end - e);
            int idx = (lane < cnt) ? d_csr[e + lane] : 0;  // coalesced
            int j = 0;
            for (; j + 4 <= cnt; j += 4) {
                int s0 = __shfl_sync(0xffffffffu, idx, j);
                int s1 = __shfl_sync(0xffffffffu, idx, j + 1);
                int s2 = __shfl_sync(0xffffffffu, idx, j + 2);
                int s3 = __shfl_sync(0xffffffffu, idx, j + 3);
                float2 h0 = __half22float2(hp[s0 * 32 + lane]);
                float2 h1 = __half22float2(hp[s1 * 32 + lane]);
                float2 h2 = __half22float2(hp[s2 * 32 + lane]);
                float2 h3 = __half22float2(hp[s3 * 32 + lane]);
                ax += (h0.x + h1.x) + (h2.x + h3.x);
                ay += (h0.y + h1.y) + (h2.y + h3.y);
            }
            for (; j < cnt; j++) {
                int s = __shfl_sync(0xffffffffu, idx, j);
                float2 hv = __half22float2(hp[s * 32 + lane]);
                ax += hv.x;
                ay += hv.y;
            }
            e += cnt;
        }
        float dd = d_deg[d];
        float2 hd = __half22float2(hp[d * 32 + lane]);
        float2 o;
        o.x = fmaf(ax + hd.x, dd, bias[2 * lane]);
        o.y = fmaf(ay + hd.y, dd, bias[2 * lane + 1]);
        *reinterpret_cast<float2*>(&d_agg[d * 64 + lane * 2]) = o;
    } else {
        const __half* hs = d_h16;  // 32 half per node row
        float a = 0.f;
        while (e < end) {
            int cnt = min(32, end - e);
            int idx = (lane < cnt) ? d_csr[e + lane] : 0;  // coalesced
            int j = 0;
            for (; j + 4 <= cnt; j += 4) {
                int s0 = __shfl_sync(0xffffffffu, idx, j);
                int s1 = __shfl_sync(0xffffffffu, idx, j + 1);
                int s2 = __shfl_sync(0xffffffffu, idx, j + 2);
                int s3 = __shfl_sync(0xffffffffu, idx, j + 3);
                float h0 = __half2float(hs[s0 * 32 + lane]);
                float h1 = __half2float(hs[s1 * 32 + lane]);
                float h2 = __half2float(hs[s2 * 32 + lane]);
                float h3 = __half2float(hs[s3 * 32 + lane]);
                a += (h0 + h1) + (h2 + h3);
            }
            for (; j < cnt; j++) {
                int s = __shfl_sync(0xffffffffu, idx, j);
                a += __half2float(hs[s * 32 + lane]);
            }
            e += cnt;
        }
        float dd = d_deg[d];
        float hd = __half2float(hs[d * 32 + lane]);
        d_agg[d * 32 + lane] = fmaf(a + hd, dd, bias[lane]);
    }
}

// ---------------- BN stats (streaming read of d_agg) -------------------------
template <int FOUT>
__global__ void bn_stats(float* __restrict__ bnout) {
    int t = blockIdx.x * blockDim.x + threadIdx.x;  // 65536 threads
    int c = t % FOUT;
    int r = t / FOUT;
    const int step = (256 * 256) / FOUT;
    float s = 0.f, ss = 0.f;
    for (; r < NN; r += step) {
        float v = d_agg[r * FOUT + c];
        s += v;
        ss = fmaf(v, v, ss);
    }
    atomicAdd(&bnout[c], s);
    atomicAdd(&bnout[64 + c], ss);
}

// ---------------- pooling (fused final BN+ReLU) + classifier -----------------
__global__ void pool_add(const int* __restrict__ batch, const float* __restrict__ bnin,
                         const float* __restrict__ g, const float* __restrict__ be) {
    __shared__ float scale[32], shift[32];
    int tid = threadIdx.x;
    if (tid < 32) {
        const float invn = 1.f / (float)NN;
        float mu = bnin[tid] * invn;
        float var = bnin[64 + tid] * invn - mu * mu;
        float s = g[tid] * rsqrtf(var + 1e-5f);
        scale[tid] = s;
        shift[tid] = fmaf(-mu, s, be[tid]);
    }
    __syncthreads();
    int i = blockIdx.x * blockDim.x + tid;
    if (i >= NN * 8) return;
    int n = i >> 3, c = i & 7;
    int g_ = batch[n];
    const float4 v = *reinterpret_cast<const float4*>(&d_agg[n * 32 + c * 4]);
    int cb = c * 4;
    float a  = fmaxf(fmaf(v.x, scale[cb],     shift[cb]),     0.f);
    float b  = fmaxf(fmaf(v.y, scale[cb + 1], shift[cb + 1]), 0.f);
    float c2 = fmaxf(fmaf(v.z, scale[cb + 2], shift[cb + 2]), 0.f);
    float d  = fmaxf(fmaf(v.w, scale[cb + 3], shift[cb + 3]), 0.f);
    red4(&d_pool[g_ * 32 + cb], a, b, c2, d);
    if (c == 0) atomicAdd(&d_cnt[g_], 1.f);
}

__global__ void classify(const float* __restrict__ Wl, const float* __restrict__ bl,
                         float* __restrict__ out) {
    int g = blockIdx.x * blockDim.x + threadIdx.x;
    if (g >= GG) return;
    float inv = 1.f / fmaxf(d_cnt[g], 1.f);
    float lo[CC];
#pragma unroll
    for (int c = 0; c < CC; c++) lo[c] = bl[c];
#pragma unroll
    for (int k = 0; k < 32; k++) {
        float p = d_pool[g * 32 + k] * inv;
#pragma unroll
        for (int c = 0; c < CC; c++) lo[c] = fmaf(p, Wl[k * CC + c], lo[c]);
    }
    float m = lo[0];
#pragma unroll
    for (int c = 1; c < CC; c++) m = fmaxf(m, lo[c]);
    float s = 0.f;
#pragma unroll
    for (int c = 0; c < CC; c++) { lo[c] = expf(lo[c] - m); s += lo[c]; }
    float is = 1.f / s;
#pragma unroll
    for (int c = 0; c < CC; c++) out[g * CC + c] = lo[c] * is;
}

// ---------------- launch -----------------------------------------------------
extern "C" void kernel_launch(void* const* d_in, const int* in_sizes, int n_in,
                              void* d_out, int out_size) {
    const float* x   = (const float*)d_in[0];
    const int* esrc  = (const int*)d_in[1];
    const int* edst  = (const int*)d_in[2];
    const int* batch = (const int*)d_in[3];
    const float* W1 = (const float*)d_in[4];   const float* b1 = (const float*)d_in[5];
    const float* W2 = (const float*)d_in[6];   const float* b2 = (const float*)d_in[7];
    const float* W4 = (const float*)d_in[8];   const float* b4 = (const float*)d_in[9];
    const float* W3 = (const float*)d_in[10];  const float* b3 = (const float*)d_in[11];
    const float* g1 = (const float*)d_in[12];  const float* be1 = (const float*)d_in[13];
    const float* g2 = (const float*)d_in[14];  const float* be2 = (const float*)d_in[15];
    const float* g4 = (const float*)d_in[16];  const float* be4 = (const float*)d_in[17];
    const float* g3 = (const float*)d_in[18];  const float* be3 = (const float*)d_in[19];
    const float* Wl = (const float*)d_in[20];  const float* bl = (const float*)d_in[21];
    float* out = (float*)d_out;

    float* bn0;  cudaGetSymbolAddress((void**)&bn0, d_bnbuf);
    float* bn1 = bn0 + 128;
    void* p_cnts; cudaGetSymbolAddress(&p_cnts, d_cnts);
    void* p_pool; cudaGetSymbolAddress(&p_pool, d_pool);
    void* p_cnt;  cudaGetSymbolAddress(&p_cnt, d_cnt);

    // setup: degrees + CSR by dst (zeroing via capturable memsets)
    cudaMemsetAsync(p_cnts, 0, NN * sizeof(int), 0);
    cudaMemsetAsync(p_pool, 0, GG * 32 * sizeof(float), 0);
    cudaMemsetAsync(p_cnt, 0, GG * sizeof(float), 0);
    count_deg<<<(EE + 255) / 256, 256>>>(edst);
    scan_bsum<<<NB, 256>>>();
    scan_final<<<NB, 256>>>();
    fill_csr<<<(EE + 255) / 256, 256>>>(esrc, edst);

    // layer 1 (conv1): x -> 64 ; stats -> bn0
    gemm_k<64><<<(NN + 63) / 64, 256>>>(x, W1, nullptr, nullptr, nullptr, bn0);
    gather_k<64><<<(NN * 32 + 255) / 256, 256>>>(b1);
    bn_stats<64><<<256, 256>>>(bn0);

    // layer 2 (conv2): BN1 -> 64 ; stats -> bn1
    gemm_k<64><<<(NN + 63) / 64, 256>>>(nullptr, W2, bn0, g1, be1, bn1);
    gather_k<64><<<(NN * 32 + 255) / 256, 256>>>(b2);
    bn_stats<64><<<256, 256>>>(bn1);

    // layer 3 (conv4): BN2 -> 64 ; stats -> bn0
    gemm_k<64><<<(NN + 63) / 64, 256>>>(nullptr, W4, bn1, g2, be2, bn0);
    gather_k<64><<<(NN * 32 + 255) / 256, 256>>>(b4);
    bn_stats<64><<<256, 256>>>(bn0);

    // layer 4 (conv3): BN4 -> 32 ; stats -> bn1
    gemm_k<32><<<(NN + 127) / 128, 256>>>(nullptr, W3, bn0, g4, be4, bn1);
    gather_k<32><<<(NN * 32 + 255) / 256, 256>>>(b3);
    bn_stats<32><<<256, 256>>>(bn1);

    // pool (fused BN3+ReLU) + classifier
    pool_add<<<(NN * 8 + 255) / 256, 256>>>(batch, bn1, g3, be3);
    classify<<<1, 256>>>(Wl, bl, out);
}